// round 15
// baseline (speedup 1.0000x reference)
#include <cuda_runtime.h>
#include <cuda_bf16.h>

#define Bb 8
#define Cc 256
#define Hh 224
#define Ww 224
#define HW (Hh * Ww)              // 50176
#define PIX2 512                  // pixels per K1 block (128 float4 groups)
#define NCH2 (HW / PIX2)          // 98 chunks per batch
#define RSEG 14                   // rows per thread in K3
#define NSEG 4
#define RS (RSEG * NSEG)          // 56 rows per K3 block

// Scratch (__device__ globals: allocation-free)
__device__ float g_partial[NCH2 * Bb * Cc];  // per-block channel partials
__device__ float g_S[Bb * HW];               // sigmoided spatial gate
__device__ float g_ch[Bb * Cc];              // sigmoided channel gate
__device__ int   g_cnt[Bb];                  // per-batch completion counters (zero-init, self-resetting)

// sigmoid(v) = 0.5*tanh(0.5*v) + 0.5 — HW MUFU.TANH. |err| ~ 2^-12.
__device__ __forceinline__ float fsigmoid(float v) {
    float t;
    asm("tanh.approx.f32 %0, %1;" : "=f"(t) : "f"(v * 0.5f));
    return fmaf(0.5f, t, 0.5f);
}

// ---------------------------------------------------------------------------
// K1': spatial gate + channel partials, PLUS fused channel-gate epilogue.
// The 98th-finishing block of each batch (elected via int atomicAdd — only
// selects WHO computes; the reduce itself reads a fixed set in fixed order,
// so the result is bit-deterministic) reduces that batch's 98 partials and
// runs the MLP -> g_ch. Counter is reset for graph-replay determinism.
// grid = (NCH2, B), block = 256.
// ---------------------------------------------------------------------------
__global__ __launch_bounds__(256) void k1_fused(
    const float* __restrict__ x,
    const float* __restrict__ spatial_w,
    const float* __restrict__ spatial_b,
    const float* __restrict__ cc1_w,   // [64, 256]
    const float* __restrict__ cc1_b,   // [64]
    const float* __restrict__ cc2_w,   // [256, 64]
    const float* __restrict__ cc2_b)   // [256]
{
    __shared__ float s_w[Cc];
    __shared__ float sdot[4][128];
    __shared__ float s_wsum[8][128];
    __shared__ int   s_last;

    const int tid  = threadIdx.x;
    const int warp = tid >> 5;
    const int lane = tid & 31;
    const int half = warp >> 2;
    const int t    = tid & 127;
    const int chunk = blockIdx.x;
    const int b     = blockIdx.y;

    s_w[tid] = spatial_w[tid];
    __syncthreads();

    const float4* xb = reinterpret_cast<const float4*>(
        x + (size_t)b * Cc * HW + (size_t)chunk * PIX2);
    const int cs4 = HW / 4;
    const int cbase = half * 128;

    float d0 = 0.f, d1 = 0.f, d2 = 0.f, d3 = 0.f;

    #pragma unroll 16
    for (int c = 0; c < 128; ++c) {
        float4 v = __ldg(&xb[(size_t)(cbase + c) * cs4 + t]);
        float wv = s_w[cbase + c];
        d0 = fmaf(v.x, wv, d0);
        d1 = fmaf(v.y, wv, d1);
        d2 = fmaf(v.z, wv, d2);
        d3 = fmaf(v.w, wv, d3);
        float cs = (v.x + v.y) + (v.z + v.w);
        cs += __shfl_down_sync(0xFFFFFFFFu, cs, 16);
        cs += __shfl_down_sync(0xFFFFFFFFu, cs, 8);
        cs += __shfl_down_sync(0xFFFFFFFFu, cs, 4);
        cs += __shfl_down_sync(0xFFFFFFFFu, cs, 2);
        cs += __shfl_down_sync(0xFFFFFFFFu, cs, 1);
        if (lane == 0) s_wsum[warp][c] = cs;
    }

    if (half == 0) {
        sdot[0][t] = d0; sdot[1][t] = d1; sdot[2][t] = d2; sdot[3][t] = d3;
    }
    __syncthreads();

    // One coalesced 256-float channel partial per block.
    {
        float s = s_wsum[half * 4 + 0][t] + s_wsum[half * 4 + 1][t]
                + s_wsum[half * 4 + 2][t] + s_wsum[half * 4 + 3][t];
        g_partial[((size_t)chunk * Bb + b) * Cc + tid] = s;
    }

    // Spatial gate.
    if (half == 1) {
        const float sb = spatial_b[0];
        float4 g;
        g.x = fsigmoid(d0 + sdot[0][t] + sb);
        g.y = fsigmoid(d1 + sdot[1][t] + sb);
        g.z = fsigmoid(d2 + sdot[2][t] + sb);
        g.w = fsigmoid(d3 + sdot[3][t] + sb);
        reinterpret_cast<float4*>(g_S + (size_t)b * HW + (size_t)chunk * PIX2)[t] = g;
    }

    // ---- fused K2: last-finishing block of this batch does the reduce+MLP ----
    __threadfence();                       // make g_partial visible chip-wide
    __syncthreads();                       // all threads' stores done before ticket
    if (tid == 0) {
        int ticket = atomicAdd(&g_cnt[b], 1);
        s_last = (ticket == NCH2 - 1);
        if (s_last) g_cnt[b] = 0;          // reset for next graph replay
    }
    __syncthreads();
    if (!s_last) return;

    // Elected block: reduce 98 partials (fixed order -> deterministic) + MLP.
    // Reuse sdot/s_wsum storage for s_avg/s_hid.
    float* s_avg = &sdot[0][0];            // 256 floats
    float* s_hid = &s_wsum[0][0];          // 64 floats

    float s = 0.f;
    #pragma unroll 7
    for (int ch = 0; ch < NCH2; ++ch)
        s += g_partial[((size_t)ch * Bb + b) * Cc + tid];
    s_avg[tid] = s * (1.0f / (float)HW);
    __syncthreads();

    if (tid < Cc / 4) {
        float acc = cc1_b[tid];
        const float* wrow = cc1_w + tid * Cc;
        #pragma unroll 4
        for (int c = 0; c < Cc; ++c) acc = fmaf(s_avg[c], wrow[c], acc);
        s_hid[tid] = fmaxf(acc, 0.f);
    }
    __syncthreads();

    float acc = cc2_b[tid];
    const float* wrow = cc2_w + tid * (Cc / 4);
    #pragma unroll
    for (int j = 0; j < Cc / 4; ++j) acc = fmaf(s_hid[j], wrow[j], acc);
    g_ch[b * Cc + tid] = fsigmoid(acc);
}

// ---------------------------------------------------------------------------
// K3 (R13 config — at its mixed-R/W DRAM ceiling, do not touch):
// vectorized 3x3 box stencil + fused gating, RSEG=14 fully unrolled,
// scalar L1-hit halo loads, HW-tanh sigmoid, __stwt streaming stores.
// grid = (4, B*C), block = 224 (56 col-groups x 4 row-segments)
// ---------------------------------------------------------------------------
__global__ __launch_bounds__(224) void k3_edge_and_gate(
    const float* __restrict__ x,
    float* __restrict__ out)
{
    const int t   = threadIdx.x;
    const int c4  = t % 56;            // float4 column group 0..55
    const int seg = t / 56;            // row segment 0..3
    const int col = c4 * 4;

    const int plane = blockIdx.y;      // b*C + c
    const int b     = plane >> 8;
    const int rst   = blockIdx.x * RS + seg * RSEG;

    const float* xp = x + (size_t)plane * HW;

    auto ldrow = [&](int r, float& lf, float& rf) -> float4 {
        if ((unsigned)r >= (unsigned)Hh) {
            lf = 0.f; rf = 0.f;
            return make_float4(0.f, 0.f, 0.f, 0.f);
        }
        const float* row = xp + r * Ww;
        float4 v = __ldg(reinterpret_cast<const float4*>(row + col));
        lf = (c4 > 0)  ? __ldg(row + col - 1) : 0.f;
        rf = (c4 < 55) ? __ldg(row + col + 4) : 0.f;
        return v;
    };
    auto hs = [](float4 v, float l, float r) -> float4 {
        float t1 = v.x + v.y;
        float t2 = v.z + v.w;
        return make_float4(l + t1, t1 + v.z, v.y + t2, t2 + r);
    };

    float lf, rf;
    float4 vA = ldrow(rst - 1, lf, rf);
    float4 hm = hs(vA, lf, rf);
    float4 vc = ldrow(rst, lf, rf);
    float4 hc = hs(vc, lf, rf);

    const float K = __ldg(&g_ch[plane]);
    const float* gSp = g_S + (size_t)b * HW + (size_t)rst * Ww + col;
    float*       op  = out + (size_t)plane * HW + (size_t)rst * Ww + col;

    #pragma unroll
    for (int i = 0; i < RSEG; ++i) {
        float4 vp = ldrow(rst + i + 1, lf, rf);
        float4 hp = hs(vp, lf, rf);
        float4 sg = __ldg(reinterpret_cast<const float4*>(gSp + i * Ww));

        float4 o;
        o.x = vc.x * (sg.x * K * fsigmoid(fmaf(9.f, vc.x, -((hm.x + hc.x) + hp.x))));
        o.y = vc.y * (sg.y * K * fsigmoid(fmaf(9.f, vc.y, -((hm.y + hc.y) + hp.y))));
        o.z = vc.z * (sg.z * K * fsigmoid(fmaf(9.f, vc.z, -((hm.z + hc.z) + hp.z))));
        o.w = vc.w * (sg.w * K * fsigmoid(fmaf(9.f, vc.w, -((hm.w + hc.w) + hp.w))));
        __stwt(reinterpret_cast<float4*>(op + i * Ww), o);

        hm = hc; hc = hp; vc = vp;
    }
}

// ---------------------------------------------------------------------------
extern "C" void kernel_launch(void* const* d_in, const int* in_sizes, int n_in,
                              void* d_out, int out_size)
{
    const float* x         = (const float*)d_in[0];
    const float* spatial_w = (const float*)d_in[1];
    const float* spatial_b = (const float*)d_in[2];
    const float* cc1_w     = (const float*)d_in[3];
    const float* cc1_b     = (const float*)d_in[4];
    const float* cc2_w     = (const float*)d_in[5];
    const float* cc2_b     = (const float*)d_in[6];
    float* out             = (float*)d_out;

    dim3 g1(NCH2, Bb);
    k1_fused<<<g1, 256>>>(x, spatial_w, spatial_b, cc1_w, cc1_b, cc2_w, cc2_b);

    dim3 g3(Hh / RS, Bb * Cc);
    k3_edge_and_gate<<<g3, 224>>>(x, out);
}

// round 16
// speedup vs baseline: 1.0577x; 1.0577x over previous
#include <cuda_runtime.h>
#include <cuda_bf16.h>

#define Bb 8
#define Cc 256
#define Hh 224
#define Ww 224
#define HW (Hh * Ww)              // 50176
#define PIX2 512                  // pixels per K1 block (128 float4 groups)
#define NCH2 (HW / PIX2)          // 98 chunks per batch
#define CGRP 7                    // chunks per K2a block (98 = 14*7)
#define NGRP (NCH2 / CGRP)        // 14
#define RSEG 14                   // rows per thread in K3
#define NSEG 4
#define RS (RSEG * NSEG)          // 56 rows per K3 block

// Scratch (__device__ globals: allocation-free)
__device__ float g_partial[NCH2 * Bb * Cc];  // per-block channel partials
__device__ float g_p2[NGRP * Bb * Cc];       // stage-2 partials
__device__ float g_S[Bb * HW];               // sigmoided spatial gate
__device__ float g_ch[Bb * Cc];              // sigmoided channel gate

// sigmoid(v) = 0.5*tanh(0.5*v) + 0.5 — HW MUFU.TANH. |err| ~ 2^-12.
__device__ __forceinline__ float fsigmoid(float v) {
    float t;
    asm("tanh.approx.f32 %0, %1;" : "=f"(t) : "f"(v * 0.5f));
    return fmaf(0.5f, t, 0.5f);
}

// PDL: block until the preceding grid on the stream has completed (implicit
// trigger at primary block exit => full memory visibility).
__device__ __forceinline__ void pdl_wait() {
    asm volatile("griddepcontrol.wait;" ::: "memory");
}

// ---------------------------------------------------------------------------
// K1 (67.4us, at its DRAM floor): in-block channel split, gate written
// directly, one coalesced 256-float channel partial per block.
// grid = (NCH2, B), block = 256.
// ---------------------------------------------------------------------------
__global__ __launch_bounds__(256) void k1_spatial_and_sums(
    const float* __restrict__ x,
    const float* __restrict__ spatial_w,
    const float* __restrict__ spatial_b)
{
    __shared__ float s_w[Cc];
    __shared__ float sdot[4][128];
    __shared__ float s_wsum[8][128];

    const int tid  = threadIdx.x;
    const int warp = tid >> 5;
    const int lane = tid & 31;
    const int half = warp >> 2;
    const int t    = tid & 127;
    const int chunk = blockIdx.x;
    const int b     = blockIdx.y;

    s_w[tid] = spatial_w[tid];
    __syncthreads();

    const float4* xb = reinterpret_cast<const float4*>(
        x + (size_t)b * Cc * HW + (size_t)chunk * PIX2);
    const int cs4 = HW / 4;
    const int cbase = half * 128;

    float d0 = 0.f, d1 = 0.f, d2 = 0.f, d3 = 0.f;

    #pragma unroll 16
    for (int c = 0; c < 128; ++c) {
        float4 v = __ldg(&xb[(size_t)(cbase + c) * cs4 + t]);
        float wv = s_w[cbase + c];
        d0 = fmaf(v.x, wv, d0);
        d1 = fmaf(v.y, wv, d1);
        d2 = fmaf(v.z, wv, d2);
        d3 = fmaf(v.w, wv, d3);
        float cs = (v.x + v.y) + (v.z + v.w);
        cs += __shfl_down_sync(0xFFFFFFFFu, cs, 16);
        cs += __shfl_down_sync(0xFFFFFFFFu, cs, 8);
        cs += __shfl_down_sync(0xFFFFFFFFu, cs, 4);
        cs += __shfl_down_sync(0xFFFFFFFFu, cs, 2);
        cs += __shfl_down_sync(0xFFFFFFFFu, cs, 1);
        if (lane == 0) s_wsum[warp][c] = cs;
    }

    if (half == 0) {
        sdot[0][t] = d0; sdot[1][t] = d1; sdot[2][t] = d2; sdot[3][t] = d3;
    }
    __syncthreads();

    {
        float s = s_wsum[half * 4 + 0][t] + s_wsum[half * 4 + 1][t]
                + s_wsum[half * 4 + 2][t] + s_wsum[half * 4 + 3][t];
        g_partial[((size_t)chunk * Bb + b) * Cc + tid] = s;
    }

    if (half == 1) {
        const float sb = spatial_b[0];
        float4 g;
        g.x = fsigmoid(d0 + sdot[0][t] + sb);
        g.y = fsigmoid(d1 + sdot[1][t] + sb);
        g.z = fsigmoid(d2 + sdot[2][t] + sb);
        g.w = fsigmoid(d3 + sdot[3][t] + sb);
        reinterpret_cast<float4*>(g_S + (size_t)b * HW + (size_t)chunk * PIX2)[t] = g;
    }
}

// ---------------------------------------------------------------------------
// K2a: parallel stage of the channel-sum reduce (112 blocks, coalesced).
// PDL secondary: waits for K1 before reading g_partial.
// grid = (NGRP, B), block = 256
// ---------------------------------------------------------------------------
__global__ __launch_bounds__(256) void k2a_reduce(void)
{
    const int cg  = blockIdx.x;
    const int b   = blockIdx.y;
    const int tid = threadIdx.x;

    pdl_wait();

    float s = 0.f;
    #pragma unroll
    for (int j = 0; j < CGRP; ++j)
        s += g_partial[((size_t)(cg * CGRP + j) * Bb + b) * Cc + tid];
    g_p2[((size_t)cg * Bb + b) * Cc + tid] = s;
}

// ---------------------------------------------------------------------------
// K2b: final reduce (14 partials) -> avg -> MLP -> channel gate.
// PDL secondary: waits for K2a.
// grid = B, block = 256
// ---------------------------------------------------------------------------
__global__ __launch_bounds__(256) void k2b_channel_gate(
    const float* __restrict__ cc1_w,
    const float* __restrict__ cc1_b,
    const float* __restrict__ cc2_w,
    const float* __restrict__ cc2_b)
{
    __shared__ float s_avg[Cc];
    __shared__ float s_hid[Cc / 4];

    const int b   = blockIdx.x;
    const int tid = threadIdx.x;

    pdl_wait();

    float s = 0.f;
    #pragma unroll
    for (int cg = 0; cg < NGRP; ++cg)
        s += g_p2[((size_t)cg * Bb + b) * Cc + tid];
    s_avg[tid] = s * (1.0f / (float)HW);
    __syncthreads();

    if (tid < Cc / 4) {
        float acc = cc1_b[tid];
        const float* wrow = cc1_w + tid * Cc;
        #pragma unroll 4
        for (int c = 0; c < Cc; ++c) acc = fmaf(s_avg[c], wrow[c], acc);
        s_hid[tid] = fmaxf(acc, 0.f);
    }
    __syncthreads();

    float acc = cc2_b[tid];
    const float* wrow = cc2_w + tid * (Cc / 4);
    #pragma unroll
    for (int j = 0; j < Cc / 4; ++j) acc = fmaf(s_hid[j], wrow[j], acc);
    g_ch[b * Cc + tid] = fsigmoid(acc);
}

// ---------------------------------------------------------------------------
// K3 (R13 body — at its mixed-R/W DRAM ceiling): vectorized 3x3 box stencil
// + fused gating, RSEG=14 fully unrolled, scalar L1-hit halo loads, HW-tanh
// sigmoid, __stwt streaming stores. PDL secondary: issues its first 3 x-row
// loads (independent of predecessors) BEFORE the wait, overlapping its
// warm-up with K2b/K1 tail; reads g_ch/g_S only after the wait.
// grid = (4, B*C), block = 224 (56 col-groups x 4 row-segments)
// ---------------------------------------------------------------------------
__global__ __launch_bounds__(224) void k3_edge_and_gate(
    const float* __restrict__ x,
    float* __restrict__ out)
{
    const int t   = threadIdx.x;
    const int c4  = t % 56;            // float4 column group 0..55
    const int seg = t / 56;            // row segment 0..3
    const int col = c4 * 4;

    const int plane = blockIdx.y;      // b*C + c
    const int b     = plane >> 8;
    const int rst   = blockIdx.x * RS + seg * RSEG;

    const float* xp = x + (size_t)plane * HW;

    auto ldrow = [&](int r, float& lf, float& rf) -> float4 {
        if ((unsigned)r >= (unsigned)Hh) {
            lf = 0.f; rf = 0.f;
            return make_float4(0.f, 0.f, 0.f, 0.f);
        }
        const float* row = xp + r * Ww;
        float4 v = __ldg(reinterpret_cast<const float4*>(row + col));
        lf = (c4 > 0)  ? __ldg(row + col - 1) : 0.f;
        rf = (c4 < 55) ? __ldg(row + col + 4) : 0.f;
        return v;
    };
    auto hs = [](float4 v, float l, float r) -> float4 {
        float t1 = v.x + v.y;
        float t2 = v.z + v.w;
        return make_float4(l + t1, t1 + v.z, v.y + t2, t2 + r);
    };

    // Pre-wait preamble: x-only loads (do not depend on K1/K2 output).
    float lf, rf;
    float4 vA = ldrow(rst - 1, lf, rf);
    float4 hm = hs(vA, lf, rf);
    float4 vc = ldrow(rst, lf, rf);
    float4 hc = hs(vc, lf, rf);

    pdl_wait();   // predecessors complete; g_S / g_ch now visible

    const float K = __ldg(&g_ch[plane]);
    const float* gSp = g_S + (size_t)b * HW + (size_t)rst * Ww + col;
    float*       op  = out + (size_t)plane * HW + (size_t)rst * Ww + col;

    #pragma unroll
    for (int i = 0; i < RSEG; ++i) {
        float4 vp = ldrow(rst + i + 1, lf, rf);
        float4 hp = hs(vp, lf, rf);
        float4 sg = __ldg(reinterpret_cast<const float4*>(gSp + i * Ww));

        float4 o;
        o.x = vc.x * (sg.x * K * fsigmoid(fmaf(9.f, vc.x, -((hm.x + hc.x) + hp.x))));
        o.y = vc.y * (sg.y * K * fsigmoid(fmaf(9.f, vc.y, -((hm.y + hc.y) + hp.y))));
        o.z = vc.z * (sg.z * K * fsigmoid(fmaf(9.f, vc.z, -((hm.z + hc.z) + hp.z))));
        o.w = vc.w * (sg.w * K * fsigmoid(fmaf(9.f, vc.w, -((hm.w + hc.w) + hp.w))));
        __stwt(reinterpret_cast<float4*>(op + i * Ww), o);

        hm = hc; hc = hp; vc = vp;
    }
}

// ---------------------------------------------------------------------------
extern "C" void kernel_launch(void* const* d_in, const int* in_sizes, int n_in,
                              void* d_out, int out_size)
{
    const float* x         = (const float*)d_in[0];
    const float* spatial_w = (const float*)d_in[1];
    const float* spatial_b = (const float*)d_in[2];
    const float* cc1_w     = (const float*)d_in[3];
    const float* cc1_b     = (const float*)d_in[4];
    const float* cc2_w     = (const float*)d_in[5];
    const float* cc2_b     = (const float*)d_in[6];
    float* out             = (float*)d_out;

    cudaLaunchAttribute pdl;
    pdl.id = cudaLaunchAttributeProgrammaticStreamSerialization;
    pdl.val.programmaticStreamSerializationAllowed = 1;

    // K1: primary (plain launch)
    {
        cudaLaunchConfig_t cfg = {};
        cfg.gridDim  = dim3(NCH2, Bb);
        cfg.blockDim = dim3(256);
        cudaLaunchKernelEx(&cfg, k1_spatial_and_sums, x, spatial_w, spatial_b);
    }
    // K2a: PDL secondary
    {
        cudaLaunchConfig_t cfg = {};
        cfg.gridDim  = dim3(NGRP, Bb);
        cfg.blockDim = dim3(256);
        cfg.attrs = &pdl; cfg.numAttrs = 1;
        cudaLaunchKernelEx(&cfg, k2a_reduce);
    }
    // K2b: PDL secondary
    {
        cudaLaunchConfig_t cfg = {};
        cfg.gridDim  = dim3(Bb);
        cfg.blockDim = dim3(256);
        cfg.attrs = &pdl; cfg.numAttrs = 1;
        cudaLaunchKernelEx(&cfg, k2b_channel_gate, cc1_w, cc1_b, cc2_w, cc2_b);
    }
    // K3: PDL secondary
    {
        cudaLaunchConfig_t cfg = {};
        cfg.gridDim  = dim3(Hh / RS, Bb * Cc);
        cfg.blockDim = dim3(224);
        cfg.attrs = &pdl; cfg.numAttrs = 1;
        cudaLaunchKernelEx(&cfg, k3_edge_and_gate, x, out);
    }
}

// round 17
// speedup vs baseline: 1.0646x; 1.0064x over previous
#include <cuda_runtime.h>
#include <cuda_bf16.h>

#define Bb 8
#define Cc 256
#define Hh 224
#define Ww 224
#define HW (Hh * Ww)              // 50176
#define PIXQ 256                  // pixels per K1 block (64 float4 groups)
#define NCHQ (HW / PIXQ)          // 196 chunks per batch
#define CGRP 14                   // chunks per K2a block (196 = 14*14)
#define NGRP (NCHQ / CGRP)        // 14
#define RSEG 14                   // rows per thread in K3
#define NSEG 4
#define RS (RSEG * NSEG)          // 56 rows per K3 block

// Scratch (__device__ globals: allocation-free)
__device__ float g_partial[NCHQ * Bb * Cc];  // per-block channel partials
__device__ float g_p2[NGRP * Bb * Cc];       // stage-2 partials
__device__ float g_S[Bb * HW];               // sigmoided spatial gate
__device__ float g_ch[Bb * Cc];              // sigmoided channel gate

// sigmoid(v) = 0.5*tanh(0.5*v) + 0.5 — HW MUFU.TANH. |err| ~ 2^-12.
__device__ __forceinline__ float fsigmoid(float v) {
    float t;
    asm("tanh.approx.f32 %0, %1;" : "=f"(t) : "f"(v * 0.5f));
    return fmaf(0.5f, t, 0.5f);
}

// PDL: block until the preceding grid on the stream has completed.
__device__ __forceinline__ void pdl_wait() {
    asm volatile("griddepcontrol.wait;" ::: "memory");
}

// ---------------------------------------------------------------------------
// K1 v5 (quarter-split): 256 threads = 4 channel-quarters x 64 pixel groups.
// Quarter q (64 threads, 2 warps) processes channels [64q, 64q+64) over the
// SAME 256 pixels. Quarter dots combined via smem -> sigmoided gate to g_S.
// Per-warp channel sums pair-combined -> one coalesced 256-float partial.
// grid = (NCHQ, B) = (196, 8) -> ~10.6 blocks/SM -> occupancy ~100%.
// ---------------------------------------------------------------------------
__global__ __launch_bounds__(256) void k1_spatial_and_sums(
    const float* __restrict__ x,
    const float* __restrict__ spatial_w,
    const float* __restrict__ spatial_b)
{
    __shared__ float  s_w[Cc];
    __shared__ float4 sdot[3][64];     // quarters 0..2 stash their dots
    __shared__ float  s_wsum[8][64];   // per-warp channel partials

    const int tid  = threadIdx.x;
    const int warp = tid >> 5;
    const int lane = tid & 31;
    const int q    = tid >> 6;         // channel quarter 0..3
    const int t    = tid & 63;         // float4 pixel group 0..63
    const int chunk = blockIdx.x;
    const int b     = blockIdx.y;

    s_w[tid] = spatial_w[tid];
    __syncthreads();

    const float4* xb = reinterpret_cast<const float4*>(
        x + (size_t)b * Cc * HW + (size_t)chunk * PIXQ);
    const int cs4 = HW / 4;
    const int cbase = q * 64;

    float d0 = 0.f, d1 = 0.f, d2 = 0.f, d3 = 0.f;

    #pragma unroll 16
    for (int c = 0; c < 64; ++c) {
        float4 v = __ldg(&xb[(size_t)(cbase + c) * cs4 + t]);
        float wv = s_w[cbase + c];
        d0 = fmaf(v.x, wv, d0);
        d1 = fmaf(v.y, wv, d1);
        d2 = fmaf(v.z, wv, d2);
        d3 = fmaf(v.w, wv, d3);
        float cs = (v.x + v.y) + (v.z + v.w);
        cs += __shfl_down_sync(0xFFFFFFFFu, cs, 16);
        cs += __shfl_down_sync(0xFFFFFFFFu, cs, 8);
        cs += __shfl_down_sync(0xFFFFFFFFu, cs, 4);
        cs += __shfl_down_sync(0xFFFFFFFFu, cs, 2);
        cs += __shfl_down_sync(0xFFFFFFFFu, cs, 1);
        if (lane == 0) s_wsum[warp][c] = cs;
    }

    if (q < 3) sdot[q][t] = make_float4(d0, d1, d2, d3);
    __syncthreads();

    // One coalesced 256-float channel partial per block.
    // tid <-> channel: quarter tid>>6 covers channels [64*(tid>>6), ..+64);
    // each channel's block sum = its quarter's two warps combined.
    {
        const int qq = tid >> 6;
        const int cl = tid & 63;
        float s = s_wsum[2 * qq][cl] + s_wsum[2 * qq + 1][cl];
        g_partial[((size_t)chunk * Bb + b) * Cc + tid] = s;
    }

    // Spatial gate (quarter 3 combines all four quarter-dots).
    if (q == 3) {
        const float sb = spatial_b[0];
        float4 a0 = sdot[0][t], a1 = sdot[1][t], a2 = sdot[2][t];
        float4 g;
        g.x = fsigmoid(((d0 + a0.x) + (a1.x + a2.x)) + sb);
        g.y = fsigmoid(((d1 + a0.y) + (a1.y + a2.y)) + sb);
        g.z = fsigmoid(((d2 + a0.z) + (a1.z + a2.z)) + sb);
        g.w = fsigmoid(((d3 + a0.w) + (a1.w + a2.w)) + sb);
        reinterpret_cast<float4*>(g_S + (size_t)b * HW + (size_t)chunk * PIXQ)[t] = g;
    }
}

// ---------------------------------------------------------------------------
// K2a: parallel stage of the channel-sum reduce (112 blocks, coalesced).
// PDL secondary: waits for K1 before reading g_partial.
// grid = (NGRP, B), block = 256
// ---------------------------------------------------------------------------
__global__ __launch_bounds__(256) void k2a_reduce(void)
{
    const int cg  = blockIdx.x;
    const int b   = blockIdx.y;
    const int tid = threadIdx.x;

    pdl_wait();

    float s = 0.f;
    #pragma unroll
    for (int j = 0; j < CGRP; ++j)
        s += g_partial[((size_t)(cg * CGRP + j) * Bb + b) * Cc + tid];
    g_p2[((size_t)cg * Bb + b) * Cc + tid] = s;
}

// ---------------------------------------------------------------------------
// K2b: final reduce (14 partials) -> avg -> MLP -> channel gate.
// PDL secondary: waits for K2a.
// grid = B, block = 256
// ---------------------------------------------------------------------------
__global__ __launch_bounds__(256) void k2b_channel_gate(
    const float* __restrict__ cc1_w,
    const float* __restrict__ cc1_b,
    const float* __restrict__ cc2_w,
    const float* __restrict__ cc2_b)
{
    __shared__ float s_avg[Cc];
    __shared__ float s_hid[Cc / 4];

    const int b   = blockIdx.x;
    const int tid = threadIdx.x;

    pdl_wait();

    float s = 0.f;
    #pragma unroll
    for (int cg = 0; cg < NGRP; ++cg)
        s += g_p2[((size_t)cg * Bb + b) * Cc + tid];
    s_avg[tid] = s * (1.0f / (float)HW);
    __syncthreads();

    if (tid < Cc / 4) {
        float acc = cc1_b[tid];
        const float* wrow = cc1_w + tid * Cc;
        #pragma unroll 4
        for (int c = 0; c < Cc; ++c) acc = fmaf(s_avg[c], wrow[c], acc);
        s_hid[tid] = fmaxf(acc, 0.f);
    }
    __syncthreads();

    float acc = cc2_b[tid];
    const float* wrow = cc2_w + tid * (Cc / 4);
    #pragma unroll
    for (int j = 0; j < Cc / 4; ++j) acc = fmaf(s_hid[j], wrow[j], acc);
    g_ch[b * Cc + tid] = fsigmoid(acc);
}

// ---------------------------------------------------------------------------
// K3 (at its mixed-R/W DRAM ceiling — frozen): vectorized 3x3 box stencil
// + fused gating, RSEG=14 fully unrolled, scalar L1-hit halo loads, HW-tanh
// sigmoid, __stwt streaming stores, PDL pre-wait x preamble.
// grid = (4, B*C), block = 224 (56 col-groups x 4 row-segments)
// ---------------------------------------------------------------------------
__global__ __launch_bounds__(224) void k3_edge_and_gate(
    const float* __restrict__ x,
    float* __restrict__ out)
{
    const int t   = threadIdx.x;
    const int c4  = t % 56;            // float4 column group 0..55
    const int seg = t / 56;            // row segment 0..3
    const int col = c4 * 4;

    const int plane = blockIdx.y;      // b*C + c
    const int b     = plane >> 8;
    const int rst   = blockIdx.x * RS + seg * RSEG;

    const float* xp = x + (size_t)plane * HW;

    auto ldrow = [&](int r, float& lf, float& rf) -> float4 {
        if ((unsigned)r >= (unsigned)Hh) {
            lf = 0.f; rf = 0.f;
            return make_float4(0.f, 0.f, 0.f, 0.f);
        }
        const float* row = xp + r * Ww;
        float4 v = __ldg(reinterpret_cast<const float4*>(row + col));
        lf = (c4 > 0)  ? __ldg(row + col - 1) : 0.f;
        rf = (c4 < 55) ? __ldg(row + col + 4) : 0.f;
        return v;
    };
    auto hs = [](float4 v, float l, float r) -> float4 {
        float t1 = v.x + v.y;
        float t2 = v.z + v.w;
        return make_float4(l + t1, t1 + v.z, v.y + t2, t2 + r);
    };

    // Pre-wait preamble: x-only loads (do not depend on predecessors).
    float lf, rf;
    float4 vA = ldrow(rst - 1, lf, rf);
    float4 hm = hs(vA, lf, rf);
    float4 vc = ldrow(rst, lf, rf);
    float4 hc = hs(vc, lf, rf);

    pdl_wait();   // predecessors complete; g_S / g_ch now visible

    const float K = __ldg(&g_ch[plane]);
    const float* gSp = g_S + (size_t)b * HW + (size_t)rst * Ww + col;
    float*       op  = out + (size_t)plane * HW + (size_t)rst * Ww + col;

    #pragma unroll
    for (int i = 0; i < RSEG; ++i) {
        float4 vp = ldrow(rst + i + 1, lf, rf);
        float4 hp = hs(vp, lf, rf);
        float4 sg = __ldg(reinterpret_cast<const float4*>(gSp + i * Ww));

        float4 o;
        o.x = vc.x * (sg.x * K * fsigmoid(fmaf(9.f, vc.x, -((hm.x + hc.x) + hp.x))));
        o.y = vc.y * (sg.y * K * fsigmoid(fmaf(9.f, vc.y, -((hm.y + hc.y) + hp.y))));
        o.z = vc.z * (sg.z * K * fsigmoid(fmaf(9.f, vc.z, -((hm.z + hc.z) + hp.z))));
        o.w = vc.w * (sg.w * K * fsigmoid(fmaf(9.f, vc.w, -((hm.w + hc.w) + hp.w))));
        __stwt(reinterpret_cast<float4*>(op + i * Ww), o);

        hm = hc; hc = hp; vc = vp;
    }
}

// ---------------------------------------------------------------------------
extern "C" void kernel_launch(void* const* d_in, const int* in_sizes, int n_in,
                              void* d_out, int out_size)
{
    const float* x         = (const float*)d_in[0];
    const float* spatial_w = (const float*)d_in[1];
    const float* spatial_b = (const float*)d_in[2];
    const float* cc1_w     = (const float*)d_in[3];
    const float* cc1_b     = (const float*)d_in[4];
    const float* cc2_w     = (const float*)d_in[5];
    const float* cc2_b     = (const float*)d_in[6];
    float* out             = (float*)d_out;

    cudaLaunchAttribute pdl;
    pdl.id = cudaLaunchAttributeProgrammaticStreamSerialization;
    pdl.val.programmaticStreamSerializationAllowed = 1;

    // K1: primary (plain launch)
    {
        cudaLaunchConfig_t cfg = {};
        cfg.gridDim  = dim3(NCHQ, Bb);
        cfg.blockDim = dim3(256);
        cudaLaunchKernelEx(&cfg, k1_spatial_and_sums, x, spatial_w, spatial_b);
    }
    // K2a: PDL secondary
    {
        cudaLaunchConfig_t cfg = {};
        cfg.gridDim  = dim3(NGRP, Bb);
        cfg.blockDim = dim3(256);
        cfg.attrs = &pdl; cfg.numAttrs = 1;
        cudaLaunchKernelEx(&cfg, k2a_reduce);
    }
    // K2b: PDL secondary
    {
        cudaLaunchConfig_t cfg = {};
        cfg.gridDim  = dim3(Bb);
        cfg.blockDim = dim3(256);
        cfg.attrs = &pdl; cfg.numAttrs = 1;
        cudaLaunchKernelEx(&cfg, k2b_channel_gate, cc1_w, cc1_b, cc2_w, cc2_b);
    }
    // K3: PDL secondary
    {
        cudaLaunchConfig_t cfg = {};
        cfg.gridDim  = dim3(Hh / RS, Bb * Cc);
        cfg.blockDim = dim3(224);
        cfg.attrs = &pdl; cfg.numAttrs = 1;
        cudaLaunchKernelEx(&cfg, k3_edge_and_gate, x, out);
    }
}